// round 3
// baseline (speedup 1.0000x reference)
#include <cuda_runtime.h>

// RoiPoolingConv: bilinear 7x7 ROI pooling over NHWC feat (1,200,200,512) fp32.
// out shape (1, 300, 7, 7, 512) fp32.
//
// d_in[0]: feat  float32  [1,200,200,512]
// d_in[1]: rois  int32    [1,300,4]  (x0, y0, w, h)
//
// R3: 256-bit feat loads (LDG.256 w/ L2::evict_last), 2 cells per 128-thread
//     block (64 threads/cell x 8 floats/thread), streaming stores for out.

#define POOL 7
#define NUM_ROIS 300
#define FH 200
#define FW 200
#define FC 512

struct F8 { float v[8]; };

// 256-bit non-coherent load with L2 evict_last (keep feat resident in L2).
__device__ __forceinline__ F8 ld_feat8(const float* p) {
    F8 r;
    unsigned a0, a1, a2, a3, a4, a5, a6, a7;
    asm volatile(
        "ld.global.nc.L2::evict_last.v8.b32 {%0,%1,%2,%3,%4,%5,%6,%7}, [%8];"
        : "=r"(a0), "=r"(a1), "=r"(a2), "=r"(a3),
          "=r"(a4), "=r"(a5), "=r"(a6), "=r"(a7)
        : "l"(p));
    r.v[0] = __int_as_float(a0); r.v[1] = __int_as_float(a1);
    r.v[2] = __int_as_float(a2); r.v[3] = __int_as_float(a3);
    r.v[4] = __int_as_float(a4); r.v[5] = __int_as_float(a5);
    r.v[6] = __int_as_float(a6); r.v[7] = __int_as_float(a7);
    return r;
}

__global__ __launch_bounds__(128, 8)
void roi_pool_kernel(const float* __restrict__ feat,
                     const int* __restrict__ rois,
                     float* __restrict__ out) {
    const int roi  = blockIdx.x;          // 0..299
    const int pair = blockIdx.y;          // 0..24
    const int half = threadIdx.x >> 6;    // 0: cellA, 1: cellB
    const int lane = threadIdx.x & 63;    // thread within cell: floats [lane*8, lane*8+8)

    int cell = pair + half * 25;          // A: 0..24, B: 25..49
    const bool valid = (cell < POOL * POOL);
    if (!valid) cell = pair;              // dup A's geometry; store suppressed

    const int4 r = __ldg(((const int4*)rois) + roi);
    const int x0 = r.x, y0 = r.y, w = r.z, h = r.w;

    const int py = cell / POOL;
    const int px = cell - py * POOL;

    // Match reference math exactly:
    //   sy = py * (h/7), y_lo = floor(sy), y_hi = min(y_lo+1, h-1), fy = sy - y_lo
    const float sy = (float)py * ((float)h / (float)POOL);
    const float sx = (float)px * ((float)w / (float)POOL);
    const int y_lo = (int)floorf(sy);
    const int x_lo = (int)floorf(sx);
    const int y_hi = min(y_lo + 1, h - 1);
    const int x_hi = min(x_lo + 1, w - 1);
    const float fy = sy - (float)y_lo;
    const float fx = sx - (float)x_lo;

    const int ay_lo = y0 + y_lo, ay_hi = y0 + y_hi;
    const int ax_lo = x0 + x_lo, ax_hi = x0 + x_hi;

    const int coff = lane * 8;  // channel offset for this thread
    const float* p00 = feat + ((size_t)ay_lo * FW + ax_lo) * FC + coff;
    const float* p01 = feat + ((size_t)ay_lo * FW + ax_hi) * FC + coff;
    const float* p10 = feat + ((size_t)ay_hi * FW + ax_lo) * FC + coff;
    const float* p11 = feat + ((size_t)ay_hi * FW + ax_hi) * FC + coff;

    // 4 independent 32B loads in flight per thread.
    const F8 v00 = ld_feat8(p00);
    const F8 v01 = ld_feat8(p01);
    const F8 v10 = ld_feat8(p10);
    const F8 v11 = ld_feat8(p11);

    const float gx = 1.0f - fx;
    const float gy = 1.0f - fy;

    float o[8];
#pragma unroll
    for (int i = 0; i < 8; i++) {
        const float top = v00.v[i] * gx + v01.v[i] * fx;
        const float bot = v10.v[i] * gx + v11.v[i] * fx;
        o[i] = top * gy + bot * fy;
    }

    if (valid) {
        float4* outp = (float4*)(out + (((size_t)roi * (POOL * POOL)) + cell) * FC + coff);
        float4 o_lo = make_float4(o[0], o[1], o[2], o[3]);
        float4 o_hi = make_float4(o[4], o[5], o[6], o[7]);
        __stcs(outp + 0, o_lo);   // streaming: evict-first, keep feat hot
        __stcs(outp + 1, o_hi);
    }
}

extern "C" void kernel_launch(void* const* d_in, const int* in_sizes, int n_in,
                              void* d_out, int out_size) {
    const float* feat = (const float*)d_in[0];
    const int*   rois = (const int*)d_in[1];
    float*       out  = (float*)d_out;

    dim3 grid(NUM_ROIS, 25);
    roi_pool_kernel<<<grid, 128>>>(feat, rois, out);
}

// round 4
// speedup vs baseline: 1.1189x; 1.1189x over previous
#include <cuda_runtime.h>

// RoiPoolingConv: bilinear 7x7 ROI pooling over NHWC feat (1,200,200,512) fp32.
// out shape (1, 300, 7, 7, 512) fp32.
//
// d_in[0]: feat  float32  [1,200,200,512]
// d_in[1]: rois  int32    [1,300,4]  (x0, y0, w, h)
//
// R4: R1 structure (1 cell / 128-thread CTA, float4 loads, high occupancy)
//     + cell-major grid order (cells of one ROI launch adjacently -> L2 locality)
//     + streaming stores (__stcs) so the output stream doesn't evict hot feat.

#define POOL 7
#define NUM_ROIS 300
#define FH 200
#define FW 200
#define FC 512

__global__ __launch_bounds__(128, 8)
void roi_pool_kernel(const float* __restrict__ feat,
                     const int* __restrict__ rois,
                     float* __restrict__ out) {
    const int cell = blockIdx.x;      // 0..48  (fast-varying: same-ROI CTAs adjacent)
    const int roi  = blockIdx.y;      // 0..299
    const int py = cell / POOL;
    const int px = cell - py * POOL;

    // ROI params (broadcast load; 4 ints contiguous)
    const int4 r = __ldg(((const int4*)rois) + roi);
    const int x0 = r.x, y0 = r.y, w = r.z, h = r.w;

    // Match reference math exactly:
    //   sy = py * (h/7), y_lo = floor(sy), y_hi = min(y_lo+1, h-1), fy = sy - y_lo
    const float sy = (float)py * ((float)h / (float)POOL);
    const float sx = (float)px * ((float)w / (float)POOL);
    const int y_lo = (int)floorf(sy);
    const int x_lo = (int)floorf(sx);
    const int y_hi = min(y_lo + 1, h - 1);
    const int x_hi = min(x_lo + 1, w - 1);
    const float fy = sy - (float)y_lo;
    const float fx = sx - (float)x_lo;

    const int ay_lo = y0 + y_lo, ay_hi = y0 + y_hi;
    const int ax_lo = x0 + x_lo, ax_hi = x0 + x_hi;

    // Channel-contiguous NHWC: feat[(y*FW + x)*FC + c]
    const float4* p00 = (const float4*)(feat + ((size_t)ay_lo * FW + ax_lo) * FC);
    const float4* p01 = (const float4*)(feat + ((size_t)ay_lo * FW + ax_hi) * FC);
    const float4* p10 = (const float4*)(feat + ((size_t)ay_hi * FW + ax_lo) * FC);
    const float4* p11 = (const float4*)(feat + ((size_t)ay_hi * FW + ax_hi) * FC);

    const int c4 = threadIdx.x;  // 0..127 -> channels c4*4..c4*4+3

    // 4 independent 16B loads in flight per thread.
    const float4 v00 = __ldg(p00 + c4);
    const float4 v01 = __ldg(p01 + c4);
    const float4 v10 = __ldg(p10 + c4);
    const float4 v11 = __ldg(p11 + c4);

    const float gx = 1.0f - fx;
    const float gy = 1.0f - fy;

    float4 o;
    {
        float top, bot;
        top = v00.x * gx + v01.x * fx;
        bot = v10.x * gx + v11.x * fx;
        o.x = top * gy + bot * fy;
        top = v00.y * gx + v01.y * fx;
        bot = v10.y * gx + v11.y * fx;
        o.y = top * gy + bot * fy;
        top = v00.z * gx + v01.z * fx;
        bot = v10.z * gx + v11.z * fx;
        o.z = top * gy + bot * fy;
        top = v00.w * gx + v01.w * fx;
        bot = v10.w * gx + v11.w * fx;
        o.w = top * gy + bot * fy;
    }

    // Streaming store: evict-first in L2, keep feat resident.
    float4* outp = (float4*)(out + (((size_t)roi * (POOL * POOL)) + cell) * FC);
    __stcs(outp + c4, o);
}

extern "C" void kernel_launch(void* const* d_in, const int* in_sizes, int n_in,
                              void* d_out, int out_size) {
    const float* feat = (const float*)d_in[0];
    const int*   rois = (const int*)d_in[1];
    float*       out  = (float*)d_out;

    dim3 grid(POOL * POOL, NUM_ROIS);   // cell-major: 49 cells of a ROI adjacent
    roi_pool_kernel<<<grid, 128>>>(feat, rois, out);
}